// round 2
// baseline (speedup 1.0000x reference)
#include <cuda_runtime.h>
#include <cuda_bf16.h>

#define B_ 8
#define C_ 128
#define O_ 128
#define H_ 64
#define W_ 64
#define HW_ (H_*W_)
#define R_ 1152   // C_ * 9 reduction length

// ---------------- scratch (no allocations allowed) ----------------
__device__ float  g_x_nhwc[B_*HW_*C_];     // 16 MB, NHWC layout of x
__device__ float2 g_smp[B_*HW_*9];         // per (b,h,w,k): pixel-space sample coords
__device__ float  g_wmT[R_*O_];            // wmT[k*128+c][o] = w_main[o][c][k]

// ---------------- Kernel A: NCHW -> NHWC transpose ----------------
__global__ void k_transpose(const float* __restrict__ x) {
    __shared__ float tile[32][33];
    int b   = blockIdx.z;
    int hw0 = blockIdx.x * 32;
    int c0  = blockIdx.y * 32;
    int tx = threadIdx.x, ty = threadIdx.y;
    #pragma unroll
    for (int m = 0; m < 32; m += 8)
        tile[ty + m][tx] = x[(size_t)(b*C_ + c0 + ty + m)*HW_ + hw0 + tx];
    __syncthreads();
    #pragma unroll
    for (int m = 0; m < 32; m += 8)
        g_x_nhwc[(size_t)(b*HW_ + hw0 + ty + m)*C_ + c0 + tx] = tile[tx][ty + m];
}

// ---------------- Kernel A2: reorder main weights ----------------
__global__ void k_wmT(const float* __restrict__ w_main) {
    int idx = blockIdx.x * 256 + threadIdx.x;     // enumerates (k,c,o), o fastest
    if (idx >= R_*O_) return;
    int o = idx & 127;
    int c = (idx >> 7) & 127;
    int k = idx >> 14;
    g_wmT[((k << 7) + c)*O_ + o] = w_main[((o << 7) + c)*9 + k];
}

// ---------------- Kernel B: 6-channel offset conv + grid coords ----------------
// Only offset channels {0,6,12} (x cumsum over i) and {1,3,5} (y cumsum over j) are used.
__global__ __launch_bounds__(256,1) void k_offset(
    const float* __restrict__ w_off, const float* __restrict__ b_off)
{
    extern __shared__ float sm[];
    float* row_s   = sm;                        // 3*66*128 floats (padded rows, x=-1..64)
    float* ws      = sm + 3*66*128;             // 6*9*128
    float* partial = ws + 6*9*128;              // 64*6*4
    float* off_s   = partial + 64*6*4;          // 64*6

    int tid = threadIdx.x;
    int b = blockIdx.x >> 6;
    int h = blockIdx.x & 63;

    // Stage 3 NHWC rows (h-1,h,h+1), zero padded left/right and out-of-range rows.
    for (int idx = tid; idx < 3*66*128; idx += 256) {
        int i   = idx / (66*128);
        int rem = idx - i*(66*128);
        int xx  = rem >> 7;         // 0..65, col xx corresponds to x = xx-1
        int c   = rem & 127;
        int y   = h - 1 + i;
        int xr  = xx - 1;
        float v = 0.f;
        if (y >= 0 && y < H_ && xr >= 0 && xr < W_)
            v = g_x_nhwc[(size_t)((b*H_ + y)*W_ + xr)*C_ + c];
        row_s[idx] = v;
    }
    // Stage the 6 needed weight channels: dd<3 -> D=6*dd (x), dd>=3 -> D=2*(dd-3)+1 (y)
    for (int idx = tid; idx < 6*9*128; idx += 256) {
        int c  = idx & 127;
        int m  = (idx >> 7) % 9;
        int dd = idx / (9*128);
        int D  = (dd < 3) ? dd*6 : (dd-3)*2 + 1;
        ws[idx] = w_off[(D*C_ + c)*9 + m];
    }
    __syncthreads();

    int warp = tid >> 5, lane = tid & 31;
    int q = warp & 3, half = warp >> 2;     // q = channel quarter, half = pixel half
    int c = (q << 5) + lane;
    for (int p = half*32; p < half*32 + 32; p++) {
        float x9[9];
        #pragma unroll
        for (int m = 0; m < 9; m++) {
            int i = m / 3, j = m % 3;
            x9[m] = row_s[(i*66 + (p + j))*C_ + c];
        }
        float acc[6];
        #pragma unroll
        for (int d = 0; d < 6; d++) {
            float a = 0.f;
            #pragma unroll
            for (int m = 0; m < 9; m++)
                a = fmaf(x9[m], ws[(d*9 + m)*C_ + c], a);
            acc[d] = a;
        }
        #pragma unroll
        for (int d = 0; d < 6; d++) {
            #pragma unroll
            for (int off = 16; off > 0; off >>= 1)
                acc[d] += __shfl_xor_sync(0xffffffffu, acc[d], off);
        }
        if (lane == 0) {
            #pragma unroll
            for (int d = 0; d < 6; d++)
                partial[(p*6 + d)*4 + q] = acc[d];
        }
    }
    __syncthreads();
    // FIX (was `if (tid < 384)` with only 256 threads -> pixels 43..63 never combined)
    for (int idx = tid; idx < 384; idx += 256) {
        int p = idx / 6, d = idx % 6;
        int D = (d < 3) ? d*6 : (d-3)*2 + 1;
        float v = b_off[D];
        #pragma unroll
        for (int qq = 0; qq < 4; qq++) v += partial[(p*6 + d)*4 + qq];
        off_s[p*6 + d] = v;
    }
    __syncthreads();
    if (tid < 64) {
        int p = tid;
        float oxs[3], oys[3];
        oxs[0] = off_s[p*6 + 0];
        oxs[1] = oxs[0] + off_s[p*6 + 1];
        oxs[2] = oxs[1] + off_s[p*6 + 2];
        oys[0] = off_s[p*6 + 3];
        oys[1] = oys[0] + off_s[p*6 + 4];
        oys[2] = oys[1] + off_s[p*6 + 5];
        float xg = p * (2.0f/63.0f) - 1.0f;
        float yg = h * (2.0f/63.0f) - 1.0f;
        float2* dst = g_smp + (size_t)((b*H_ + h)*W_ + p)*9;
        #pragma unroll
        for (int i = 0; i < 3; i++) {
            #pragma unroll
            for (int j = 0; j < 3; j++) {
                float gx = (xg + oxs[i] + 1.0f)*(W_*0.5f) - 0.5f;  // align_corners=False
                float gy = (yg + oys[j] + 1.0f)*(H_*0.5f) - 0.5f;
                dst[i*3 + j] = make_float2(gx, gy);
            }
        }
    }
}

// ---------------- Kernel C: bilinear sample + main GEMM ----------------
// Block = 32 pixels (same b,h). Phase 1: gather xs[r=k*128+c][p] into XOR-swizzled
// smem (word = r*32 + (p ^ (r&31)) -> conflict-free STS, broadcast LDS.128 reads).
// Phase 2: out[32][128] = xs[32][1152] @ wmT[1152][128], 4x4 register microtiles.
__global__ __launch_bounds__(256,1) void k_main(
    const float* __restrict__ b_main, float* __restrict__ out)
{
    extern __shared__ float sm[];
    float* xs_s = sm;             // 1152*32 floats (147456 B)
    float* ws2  = sm + R_*32;     // 64*128 floats   (32768 B), reused as out staging

    int tid = threadIdx.x;
    int bid = blockIdx.x;
    int b   = bid >> 7;
    int rem = bid & 127;
    int h   = rem >> 1;
    int w0  = (rem & 1) << 5;

    int warp = tid >> 5, lane = tid & 31;
    const float* xb = g_x_nhwc + (size_t)b*HW_*C_;

    // ---- Phase 1: 288 samples (32 px * 9 taps), one warp per sample ----
    for (int s = warp; s < 288; s += 8) {
        int p = s / 9;
        int k = s - p*9;
        float2 g = g_smp[(size_t)((b*H_ + h)*W_ + (w0 + p))*9 + k];
        float x0f = floorf(g.x), y0f = floorf(g.y);
        int ix = (int)x0f, iy = (int)y0f;
        float wx = g.x - x0f, wy = g.y - y0f;
        float w00 = (1.f-wx)*(1.f-wy), w01 = wx*(1.f-wy);
        float w10 = (1.f-wx)*wy,       w11 = wx*wy;
        bool vx0 = (unsigned)ix < (unsigned)W_, vx1 = (unsigned)(ix+1) < (unsigned)W_;
        bool vy0 = (unsigned)iy < (unsigned)H_, vy1 = (unsigned)(iy+1) < (unsigned)H_;
        w00 = (vx0 && vy0) ? w00 : 0.f;
        w01 = (vx1 && vy0) ? w01 : 0.f;
        w10 = (vx0 && vy1) ? w10 : 0.f;
        w11 = (vx1 && vy1) ? w11 : 0.f;
        int cx0 = min(max(ix,   0), W_-1), cx1 = min(max(ix+1, 0), W_-1);
        int cy0 = min(max(iy,   0), H_-1), cy1 = min(max(iy+1, 0), H_-1);
        const float* p00 = xb + (size_t)(cy0*W_ + cx0)*C_;
        const float* p01 = xb + (size_t)(cy0*W_ + cx1)*C_;
        const float* p10 = xb + (size_t)(cy1*W_ + cx0)*C_;
        const float* p11 = xb + (size_t)(cy1*W_ + cx1)*C_;
        int rbase = k << 7;
        #pragma unroll
        for (int qq = 0; qq < 4; qq++) {
            int cch = (qq << 5) + lane;
            float v = p00[cch]*w00 + p01[cch]*w01 + p10[cch]*w10 + p11[cch]*w11;
            int r = rbase + cch;
            xs_s[(r << 5) + (p ^ (r & 31))] = v;
        }
    }
    __syncthreads();

    // ---- Phase 2: GEMM, thread = (og: 4 outputs) x (pg: 4 pixels) ----
    int og = tid & 31;
    int pg = tid >> 5;
    float acc[4][4];
    #pragma unroll
    for (int i = 0; i < 4; i++)
        #pragma unroll
        for (int j = 0; j < 4; j++) acc[i][j] = 0.f;

    for (int cc = 0; cc < 18; cc++) {
        // stage 64 rows of wmT into smem (coalesced float4)
        const float4* src = (const float4*)(g_wmT + (size_t)cc*64*O_);
        float4* dst = (float4*)ws2;
        #pragma unroll
        for (int t = 0; t < 8; t++)
            dst[t*256 + tid] = src[t*256 + tid];
        __syncthreads();

        #pragma unroll 2
        for (int rr = 0; rr < 64; rr += 4) {
            #pragma unroll
            for (int s4 = 0; s4 < 4; s4++) {
                int r = cc*64 + rr + s4;                       // r & 3 == s4
                float4 xv = *(const float4*)&xs_s[(r << 5) + ((pg ^ ((r >> 2) & 7)) << 2)];
                float4 wv = *(const float4*)&ws2[(rr + s4)*O_ + (og << 2)];
                const float* xf = (const float*)&xv;
                float xp0 = xf[0 ^ s4];
                float xp1 = xf[1 ^ s4];
                float xp2 = xf[2 ^ s4];
                float xp3 = xf[3 ^ s4];
                acc[0][0] = fmaf(wv.x, xp0, acc[0][0]);
                acc[0][1] = fmaf(wv.x, xp1, acc[0][1]);
                acc[0][2] = fmaf(wv.x, xp2, acc[0][2]);
                acc[0][3] = fmaf(wv.x, xp3, acc[0][3]);
                acc[1][0] = fmaf(wv.y, xp0, acc[1][0]);
                acc[1][1] = fmaf(wv.y, xp1, acc[1][1]);
                acc[1][2] = fmaf(wv.y, xp2, acc[1][2]);
                acc[1][3] = fmaf(wv.y, xp3, acc[1][3]);
                acc[2][0] = fmaf(wv.z, xp0, acc[2][0]);
                acc[2][1] = fmaf(wv.z, xp1, acc[2][1]);
                acc[2][2] = fmaf(wv.z, xp2, acc[2][2]);
                acc[2][3] = fmaf(wv.z, xp3, acc[2][3]);
                acc[3][0] = fmaf(wv.w, xp0, acc[3][0]);
                acc[3][1] = fmaf(wv.w, xp1, acc[3][1]);
                acc[3][2] = fmaf(wv.w, xp2, acc[3][2]);
                acc[3][3] = fmaf(wv.w, xp3, acc[3][3]);
            }
        }
        __syncthreads();
    }

    // ---- Epilogue: stage in smem for coalesced STG ----
    float* outs = ws2;   // 128*33 floats fits in ws2 region
    #pragma unroll
    for (int i = 0; i < 4; i++)
        #pragma unroll
        for (int j = 0; j < 4; j++)
            outs[(og*4 + i)*33 + pg*4 + j] = acc[i][j];
    __syncthreads();
    for (int idx = tid; idx < 4096; idx += 256) {
        int o = idx >> 5, j = idx & 31;
        out[(size_t)((b*O_ + o)*H_ + h)*W_ + w0 + j] = outs[o*33 + j] + b_main[o];
    }
}

// ---------------- launch ----------------
extern "C" void kernel_launch(void* const* d_in, const int* in_sizes, int n_in,
                              void* d_out, int out_size) {
    const float* x      = (const float*)d_in[0];
    const float* w_off  = (const float*)d_in[1];
    const float* b_off  = (const float*)d_in[2];
    const float* w_main = (const float*)d_in[3];
    const float* b_main = (const float*)d_in[4];
    float* out = (float*)d_out;

    const int smemB = (3*66*128 + 6*9*128 + 64*6*4 + 64*6) * 4;   // 136704 B
    const int smemC = (R_*32 + 64*O_) * 4;                        // 180224 B
    cudaFuncSetAttribute(k_offset, cudaFuncAttributeMaxDynamicSharedMemorySize, smemB);
    cudaFuncSetAttribute(k_main,   cudaFuncAttributeMaxDynamicSharedMemorySize, smemC);

    k_transpose<<<dim3(HW_/32, C_/32, B_), dim3(32, 8)>>>(x);
    k_wmT<<<(R_*O_ + 255)/256, 256>>>(w_main);
    k_offset<<<B_*H_, 256, smemB>>>(w_off, b_off);
    k_main<<<B_*H_*2, 256, smemC>>>(b_main, out);
}

// round 4
// speedup vs baseline: 1.8626x; 1.8626x over previous
#include <cuda_runtime.h>
#include <cuda_bf16.h>
#include <cstdint>

#define B_ 8
#define C_ 128
#define O_ 128
#define H_ 64
#define W_ 64
#define HW_ (H_*W_)

// ---------------- scratch ----------------
__device__ float  g_x_nhwc[B_*HW_*C_];          // NHWC x
__device__ float2 g_smp[B_*HW_*9];              // sample coords per (b,h,w,tap)
__device__ unsigned char g_wsw[2*9*32768];      // swizzled bf16 weights [term][tap][128o x 128c]

// ---------------- helpers ----------------
__device__ __forceinline__ uint32_t smem_u32(const void* p) {
    uint32_t a;
    asm("{ .reg .u64 t; cvta.to.shared.u64 t, %1; cvt.u32.u64 %0, t; }" : "=r"(a) : "l"(p));
    return a;
}
__device__ __forceinline__ void ldsm4(uint32_t& r0, uint32_t& r1, uint32_t& r2, uint32_t& r3,
                                      uint32_t addr) {
    asm volatile("ldmatrix.sync.aligned.m8n8.x4.shared.b16 {%0,%1,%2,%3}, [%4];"
        : "=r"(r0), "=r"(r1), "=r"(r2), "=r"(r3) : "r"(addr));
}
__device__ __forceinline__ void mma16816(float* d, const uint32_t* a, uint32_t b0, uint32_t b1) {
    asm volatile("mma.sync.aligned.m16n8k16.row.col.f32.bf16.bf16.f32 "
        "{%0,%1,%2,%3}, {%4,%5,%6,%7}, {%8,%9}, {%0,%1,%2,%3};"
        : "+f"(d[0]), "+f"(d[1]), "+f"(d[2]), "+f"(d[3])
        : "r"(a[0]), "r"(a[1]), "r"(a[2]), "r"(a[3]), "r"(b0), "r"(b1));
}
#define CP_ASYNC16(dst, src) \
    asm volatile("cp.async.cg.shared.global [%0], [%1], 16;" :: "r"(dst), "l"(src))
#define CP_COMMIT() asm volatile("cp.async.commit_group;" ::: "memory")
#define CP_WAIT0()  asm volatile("cp.async.wait_group 0;" ::: "memory")

// smem map for k_main
#define SM_BIAS 0
#define SM_A_HI 1024
#define SM_A_LO (1024 + 32768)
#define SM_W_HI (1024 + 65536)
#define SM_W_LO (1024 + 98304)
#define SM_OUT  1024
#define SMEM_MAIN (1024 + 131072)   // 132096 B

// ---------------- Kernel A: NCHW -> NHWC transpose ----------------
__global__ void k_transpose(const float* __restrict__ x) {
    __shared__ float tile[32][33];
    int b   = blockIdx.z;
    int hw0 = blockIdx.x * 32;
    int c0  = blockIdx.y * 32;
    int tx = threadIdx.x, ty = threadIdx.y;
    #pragma unroll
    for (int m = 0; m < 32; m += 8)
        tile[ty + m][tx] = x[(size_t)(b*C_ + c0 + ty + m)*HW_ + hw0 + tx];
    __syncthreads();
    #pragma unroll
    for (int m = 0; m < 32; m += 8)
        g_x_nhwc[(size_t)(b*HW_ + hw0 + ty + m)*C_ + c0 + tx] = tile[tx][ty + m];
}

// ---------------- Kernel A2: split + swizzle weights ----------------
// Block (t,kk): [o][c] bf16, row = o (256B), unit-XOR swizzle:
// byte = o*256 + (((c>>3) ^ (o&7))<<4) + (c&7)*2
__global__ void k_wprep(const float* __restrict__ w_main) {
    int idx = blockIdx.x * 256 + threadIdx.x;
    if (idx >= 2*9*128*128) return;
    int c  = idx & 127;
    int o  = (idx >> 7) & 127;
    int kk = (idx >> 14) % 9;
    int t  = idx / (9*16384);
    float w = w_main[(o*C_ + c)*9 + kk];
    __nv_bfloat16 hi = __float2bfloat16(w);
    __nv_bfloat16 v  = (t == 0) ? hi : __float2bfloat16(w - __bfloat162float(hi));
    uint32_t boff = (uint32_t)(o*256 + (((c >> 3) ^ (o & 7)) << 4) + (c & 7)*2);
    *(__nv_bfloat16*)(g_wsw + (size_t)(t*9 + kk)*32768 + boff) = v;
}

// ---------------- Kernel B: 6-channel offset conv + grid coords ----------------
__global__ __launch_bounds__(256,1) void k_offset(
    const float* __restrict__ w_off, const float* __restrict__ b_off)
{
    extern __shared__ float sm[];
    float* row_s   = sm;
    float* ws      = sm + 3*66*128;
    float* partial = ws + 6*9*128;
    float* off_s   = partial + 64*6*4;

    int tid = threadIdx.x;
    int b = blockIdx.x >> 6;
    int h = blockIdx.x & 63;

    for (int idx = tid; idx < 3*66*128; idx += 256) {
        int i   = idx / (66*128);
        int rem = idx - i*(66*128);
        int xx  = rem >> 7;
        int c   = rem & 127;
        int y   = h - 1 + i;
        int xr  = xx - 1;
        float v = 0.f;
        if (y >= 0 && y < H_ && xr >= 0 && xr < W_)
            v = g_x_nhwc[(size_t)((b*H_ + y)*W_ + xr)*C_ + c];
        row_s[idx] = v;
    }
    for (int idx = tid; idx < 6*9*128; idx += 256) {
        int c  = idx & 127;
        int m  = (idx >> 7) % 9;
        int dd = idx / (9*128);
        int D  = (dd < 3) ? dd*6 : (dd-3)*2 + 1;
        ws[idx] = w_off[(D*C_ + c)*9 + m];
    }
    __syncthreads();

    int warp = tid >> 5, lane = tid & 31;
    int q = warp & 3, half = warp >> 2;
    int c = (q << 5) + lane;
    for (int p = half*32; p < half*32 + 32; p++) {
        float x9[9];
        #pragma unroll
        for (int m = 0; m < 9; m++) {
            int i = m / 3, j = m % 3;
            x9[m] = row_s[(i*66 + (p + j))*C_ + c];
        }
        float acc[6];
        #pragma unroll
        for (int d = 0; d < 6; d++) {
            float a = 0.f;
            #pragma unroll
            for (int m = 0; m < 9; m++)
                a = fmaf(x9[m], ws[(d*9 + m)*C_ + c], a);
            acc[d] = a;
        }
        #pragma unroll
        for (int d = 0; d < 6; d++) {
            #pragma unroll
            for (int off = 16; off > 0; off >>= 1)
                acc[d] += __shfl_xor_sync(0xffffffffu, acc[d], off);
        }
        if (lane == 0) {
            #pragma unroll
            for (int d = 0; d < 6; d++)
                partial[(p*6 + d)*4 + q] = acc[d];
        }
    }
    __syncthreads();
    for (int idx = tid; idx < 384; idx += 256) {
        int p = idx / 6, d = idx % 6;
        int D = (d < 3) ? d*6 : (d-3)*2 + 1;
        float v = b_off[D];
        #pragma unroll
        for (int qq = 0; qq < 4; qq++) v += partial[(p*6 + d)*4 + qq];
        off_s[p*6 + d] = v;
    }
    __syncthreads();
    if (tid < 64) {
        int p = tid;
        float oxs[3], oys[3];
        oxs[0] = off_s[p*6 + 0];
        oxs[1] = oxs[0] + off_s[p*6 + 1];
        oxs[2] = oxs[1] + off_s[p*6 + 2];
        oys[0] = off_s[p*6 + 3];
        oys[1] = oys[0] + off_s[p*6 + 4];
        oys[2] = oys[1] + off_s[p*6 + 5];
        float xg = p * (2.0f/63.0f) - 1.0f;
        float yg = h * (2.0f/63.0f) - 1.0f;
        float2* dst = g_smp + (size_t)((b*H_ + h)*W_ + p)*9;
        #pragma unroll
        for (int i = 0; i < 3; i++) {
            #pragma unroll
            for (int j = 0; j < 3; j++) {
                float gx = (xg + oxs[i] + 1.0f)*(W_*0.5f) - 0.5f;
                float gy = (yg + oys[j] + 1.0f)*(H_*0.5f) - 0.5f;
                dst[i*3 + j] = make_float2(gx, gy);
            }
        }
    }
}

// ---------------- Kernel C: sample + mma.sync bf16 GEMM ----------------
// CTA = 128 px. Per tap: cp.async weights (hi/lo 32KB each) while sampling
// 128px x 128ch into swizzled A tiles (hi/lo); then 8 warps (4 m x 2 n grid)
// run 32x64 register-tile MMA over 8 k16 steps x 3 split terms.
__global__ __launch_bounds__(256,1) void k_main(
    const float* __restrict__ b_main, float* __restrict__ out)
{
    extern __shared__ char smc[];
    uint32_t sb = smem_u32(smc);
    int tid = threadIdx.x;
    int wid = tid >> 5, lane = tid & 31;

    int bid = blockIdx.x;
    int b   = bid >> 5;
    int hw0 = (bid & 31) << 7;
    const float* xb = g_x_nhwc + (size_t)b*HW_*C_;

    if (tid < 128) *(float*)(smc + SM_BIAS + tid*4) = b_main[tid];

    int m0 = (wid & 3) << 5;     // 4 m-warps of 32 px
    int o0 = (wid >> 2) << 6;    // 2 n-warps of 64 outputs

    // per-lane ldmatrix constants
    int l7   = lane & 7;
    int arow = l7 + ((lane >> 3) & 1) * 8;   // A x4 row offset
    int au   = lane >> 4;                     // A x4 unit offset
    int brow = l7 + (lane >> 4) * 8;          // B x4 row offset
    int bu   = (lane >> 3) & 1;               // B x4 unit offset

    float acc[64];
    #pragma unroll
    for (int i = 0; i < 64; i++) acc[i] = 0.f;

    for (int kk = 0; kk < 9; kk++) {
        __syncthreads();   // prev tap's ldmatrix reads done; A/W writable

        // cp.async this tap's weights (swizzled layout is copied verbatim)
        {
            const char* wgh = (const char*)(g_wsw + (size_t)kk*32768);
            const char* wgl = (const char*)(g_wsw + (size_t)(9 + kk)*32768);
            uint32_t dh = sb + SM_W_HI + tid*16;
            uint32_t dl = sb + SM_W_LO + tid*16;
            #pragma unroll
            for (int i = 0; i < 8; i++)
                CP_ASYNC16(dh + i*4096, wgh + i*4096 + tid*16);
            #pragma unroll
            for (int i = 0; i < 8; i++)
                CP_ASYNC16(dl + i*4096, wgl + i*4096 + tid*16);
            CP_COMMIT();
        }

        // sample 16 px per warp into A_HI/A_LO
        for (int p = wid*16; p < wid*16 + 16; p++) {
            float2 g = g_smp[(size_t)(b*HW_ + hw0 + p)*9 + kk];
            float x0f = floorf(g.x), y0f = floorf(g.y);
            int ix = (int)x0f, iy = (int)y0f;
            float wx = g.x - x0f, wy = g.y - y0f;
            float w00 = (1.f-wx)*(1.f-wy), w01 = wx*(1.f-wy);
            float w10 = (1.f-wx)*wy,       w11 = wx*wy;
            bool vx0 = (unsigned)ix < (unsigned)W_, vx1 = (unsigned)(ix+1) < (unsigned)W_;
            bool vy0 = (unsigned)iy < (unsigned)H_, vy1 = (unsigned)(iy+1) < (unsigned)H_;
            w00 = (vx0 && vy0) ? w00 : 0.f;
            w01 = (vx1 && vy0) ? w01 : 0.f;
            w10 = (vx0 && vy1) ? w10 : 0.f;
            w11 = (vx1 && vy1) ? w11 : 0.f;
            int cx0 = min(max(ix,   0), W_-1), cx1 = min(max(ix+1, 0), W_-1);
            int cy0 = min(max(iy,   0), H_-1), cy1 = min(max(iy+1, 0), H_-1);
            const float2* r00 = (const float2*)(xb + (size_t)(cy0*W_ + cx0)*C_);
            const float2* r01 = (const float2*)(xb + (size_t)(cy0*W_ + cx1)*C_);
            const float2* r10 = (const float2*)(xb + (size_t)(cy1*W_ + cx0)*C_);
            const float2* r11 = (const float2*)(xb + (size_t)(cy1*W_ + cx1)*C_);
            #pragma unroll
            for (int q = 0; q < 2; q++) {
                int ci = q*32 + lane;   // channels {2ci, 2ci+1}
                float2 a00 = r00[ci], a01 = r01[ci], a10 = r10[ci], a11 = r11[ci];
                float v0 = a00.x*w00 + a01.x*w01 + a10.x*w10 + a11.x*w11;
                float v1 = a00.y*w00 + a01.y*w01 + a10.y*w10 + a11.y*w11;
                __nv_bfloat16 h0 = __float2bfloat16(v0);
                __nv_bfloat16 h1 = __float2bfloat16(v1);
                __nv_bfloat16 l0 = __float2bfloat16(v0 - __bfloat162float(h0));
                __nv_bfloat16 l1 = __float2bfloat16(v1 - __bfloat162float(h1));
                uint32_t hp = ((uint32_t)__bfloat16_as_ushort(h1) << 16) | __bfloat16_as_ushort(h0);
                uint32_t lp = ((uint32_t)__bfloat16_as_ushort(l1) << 16) | __bfloat16_as_ushort(l0);
                uint32_t boff = (uint32_t)(p*256 + (((ci >> 2) ^ (p & 7)) << 4) + (ci & 3)*4);
                *(uint32_t*)(smc + SM_A_HI + boff) = hp;
                *(uint32_t*)(smc + SM_A_LO + boff) = lp;
            }
        }
        CP_WAIT0();
        __syncthreads();   // A + W tiles ready

        // ---- MMA over 8 k16 steps ----
        #pragma unroll 2
        for (int step = 0; step < 8; step++) {
            int u0 = step << 1;
            uint32_t ah[2][4], al[2][4];
            #pragma unroll
            for (int mt = 0; mt < 2; mt++) {
                uint32_t aoff = (uint32_t)((m0 + mt*16 + arow)*256 + (((u0 + au) ^ l7) << 4));
                ldsm4(ah[mt][0], ah[mt][1], ah[mt][2], ah[mt][3], sb + SM_A_HI + aoff);
                ldsm4(al[mt][0], al[mt][1], al[mt][2], al[mt][3], sb + SM_A_LO + aoff);
            }
            #pragma unroll
            for (int np = 0; np < 4; np++) {
                uint32_t boff = (uint32_t)((o0 + np*16 + brow)*256 + (((u0 + bu) ^ l7) << 4));
                uint32_t bh0, bh1, bh2, bh3, bl0, bl1, bl2, bl3;
                ldsm4(bh0, bh1, bh2, bh3, sb + SM_W_HI + boff);
                ldsm4(bl0, bl1, bl2, bl3, sb + SM_W_LO + boff);
                #pragma unroll
                for (int mt = 0; mt < 2; mt++) {
                    float* d0 = &acc[(mt*8 + np*2    )*4];
                    float* d1 = &acc[(mt*8 + np*2 + 1)*4];
                    mma16816(d0, ah[mt], bh0, bh1);
                    mma16816(d0, al[mt], bh0, bh1);
                    mma16816(d0, ah[mt], bl0, bl1);
                    mma16816(d1, ah[mt], bh2, bh3);
                    mma16816(d1, al[mt], bh2, bh3);
                    mma16816(d1, ah[mt], bl2, bl3);
                }
            }
        }
    }

    // ---- epilogue: stage to smem (stride 132 -> conflict-free), coalesced STG ----
    __syncthreads();
    float* outs = (float*)(smc + SM_OUT);
    #pragma unroll
    for (int mt = 0; mt < 2; mt++) {
        #pragma unroll
        for (int nt = 0; nt < 8; nt++) {
            float* d = &acc[(mt*8 + nt)*4];
            int r = m0 + mt*16 + (lane >> 2);
            int o = o0 + nt*8 + (lane & 3)*2;
            outs[ o     *132 + r    ] = d[0];
            outs[(o + 1)*132 + r    ] = d[1];
            outs[ o     *132 + r + 8] = d[2];
            outs[(o + 1)*132 + r + 8] = d[3];
        }
    }
    __syncthreads();
    const float* bias = (const float*)(smc + SM_BIAS);
    for (int idx = tid; idx < 128*128; idx += 256) {
        int o = idx >> 7, px = idx & 127;
        out[(size_t)(b*O_ + o)*HW_ + hw0 + px] = outs[o*132 + px] + bias[o];
    }
}

// ---------------- launch ----------------
extern "C" void kernel_launch(void* const* d_in, const int* in_sizes, int n_in,
                              void* d_out, int out_size) {
    const float* x      = (const float*)d_in[0];
    const float* w_off  = (const float*)d_in[1];
    const float* b_off  = (const float*)d_in[2];
    const float* w_main = (const float*)d_in[3];
    const float* b_main = (const float*)d_in[4];
    float* out = (float*)d_out;

    const int smemB = (3*66*128 + 6*9*128 + 64*6*4 + 64*6) * 4;   // 136704 B
    cudaFuncSetAttribute(k_offset, cudaFuncAttributeMaxDynamicSharedMemorySize, smemB);
    cudaFuncSetAttribute(k_main,   cudaFuncAttributeMaxDynamicSharedMemorySize, SMEM_MAIN);

    k_transpose<<<dim3(HW_/32, C_/32, B_), dim3(32, 8)>>>(x);
    k_wprep<<<(2*9*128*128 + 255)/256, 256>>>(w_main);
    k_offset<<<B_*H_, 256, smemB>>>(w_off, b_off);
    k_main<<<B_*HW_/128, 256, SMEM_MAIN>>>(b_main, out);
}

// round 5
// speedup vs baseline: 2.3840x; 1.2799x over previous
#include <cuda_runtime.h>
#include <cuda_bf16.h>
#include <cstdint>

#define B_ 8
#define C_ 128
#define O_ 128
#define H_ 64
#define W_ 64
#define HW_ (H_*W_)

// ---------------- scratch ----------------
__device__ float  g_x_nhwc[B_*HW_*C_];          // NHWC x
__device__ float2 g_smp[B_*HW_*9];              // sample coords per (b,h,w,tap)
__device__ unsigned char g_wsw[2*9*32768];      // swizzled bf16 weights [term][tap][128o x 128c]

// ---------------- helpers ----------------
__device__ __forceinline__ uint32_t smem_u32(const void* p) {
    uint32_t a;
    asm("{ .reg .u64 t; cvta.to.shared.u64 t, %1; cvt.u32.u64 %0, t; }" : "=r"(a) : "l"(p));
    return a;
}
__device__ __forceinline__ void ldsm4(uint32_t& r0, uint32_t& r1, uint32_t& r2, uint32_t& r3,
                                      uint32_t addr) {
    asm volatile("ldmatrix.sync.aligned.m8n8.x4.shared.b16 {%0,%1,%2,%3}, [%4];"
        : "=r"(r0), "=r"(r1), "=r"(r2), "=r"(r3) : "r"(addr));
}
__device__ __forceinline__ void mma16816(float* d, const uint32_t* a, uint32_t b0, uint32_t b1) {
    asm volatile("mma.sync.aligned.m16n8k16.row.col.f32.bf16.bf16.f32 "
        "{%0,%1,%2,%3}, {%4,%5,%6,%7}, {%8,%9}, {%0,%1,%2,%3};"
        : "+f"(d[0]), "+f"(d[1]), "+f"(d[2]), "+f"(d[3])
        : "r"(a[0]), "r"(a[1]), "r"(a[2]), "r"(a[3]), "r"(b0), "r"(b1));
}
#define CP_ASYNC16(dst, src) \
    asm volatile("cp.async.cg.shared.global [%0], [%1], 16;" :: "r"(dst), "l"(src))
#define CP_COMMIT() asm volatile("cp.async.commit_group;" ::: "memory")
#define CP_WAIT0()  asm volatile("cp.async.wait_group 0;" ::: "memory")

// smem map for k_main (64-px tile): 97.25 KB -> 2 CTAs/SM
#define SM_BIAS 0
#define SM_A_HI 1024
#define SM_A_LO (1024 + 16384)
#define SM_W_HI (1024 + 32768)
#define SM_W_LO (1024 + 65536)
#define SM_OUT  SM_W_HI                 // reused after last MMA
#define SMEM_MAIN (1024 + 98304)        // 99328 B

// ---------------- Kernel A: NCHW -> NHWC transpose ----------------
__global__ void k_transpose(const float* __restrict__ x) {
    __shared__ float tile[32][33];
    int b   = blockIdx.z;
    int hw0 = blockIdx.x * 32;
    int c0  = blockIdx.y * 32;
    int tx = threadIdx.x, ty = threadIdx.y;
    #pragma unroll
    for (int m = 0; m < 32; m += 8)
        tile[ty + m][tx] = x[(size_t)(b*C_ + c0 + ty + m)*HW_ + hw0 + tx];
    __syncthreads();
    #pragma unroll
    for (int m = 0; m < 32; m += 8)
        g_x_nhwc[(size_t)(b*HW_ + hw0 + ty + m)*C_ + c0 + tx] = tile[tx][ty + m];
}

// ---------------- Kernel A2: split + swizzle weights ----------------
// byte = o*256 + (((c>>3) ^ (o&7))<<4) + (c&7)*2
__global__ void k_wprep(const float* __restrict__ w_main) {
    int idx = blockIdx.x * 256 + threadIdx.x;
    if (idx >= 2*9*128*128) return;
    int c  = idx & 127;
    int o  = (idx >> 7) & 127;
    int kk = (idx >> 14) % 9;
    int t  = idx / (9*16384);
    float w = w_main[(o*C_ + c)*9 + kk];
    __nv_bfloat16 hi = __float2bfloat16(w);
    __nv_bfloat16 v  = (t == 0) ? hi : __float2bfloat16(w - __bfloat162float(hi));
    uint32_t boff = (uint32_t)(o*256 + (((c >> 3) ^ (o & 7)) << 4) + (c & 7)*2);
    *(__nv_bfloat16*)(g_wsw + (size_t)(t*9 + kk)*32768 + boff) = v;
}

// ---------------- Kernel B: 6-channel offset conv + grid coords ----------------
__global__ __launch_bounds__(256,1) void k_offset(
    const float* __restrict__ w_off, const float* __restrict__ b_off)
{
    extern __shared__ float sm[];
    float* row_s   = sm;
    float* ws      = sm + 3*66*128;
    float* partial = ws + 6*9*128;
    float* off_s   = partial + 64*6*4;

    int tid = threadIdx.x;
    int b = blockIdx.x >> 6;
    int h = blockIdx.x & 63;

    for (int idx = tid; idx < 3*66*128; idx += 256) {
        int i   = idx / (66*128);
        int rem = idx - i*(66*128);
        int xx  = rem >> 7;
        int c   = rem & 127;
        int y   = h - 1 + i;
        int xr  = xx - 1;
        float v = 0.f;
        if (y >= 0 && y < H_ && xr >= 0 && xr < W_)
            v = g_x_nhwc[(size_t)((b*H_ + y)*W_ + xr)*C_ + c];
        row_s[idx] = v;
    }
    for (int idx = tid; idx < 6*9*128; idx += 256) {
        int c  = idx & 127;
        int m  = (idx >> 7) % 9;
        int dd = idx / (9*128);
        int D  = (dd < 3) ? dd*6 : (dd-3)*2 + 1;
        ws[idx] = w_off[(D*C_ + c)*9 + m];
    }
    __syncthreads();

    int warp = tid >> 5, lane = tid & 31;
    int q = warp & 3, half = warp >> 2;
    int c = (q << 5) + lane;
    for (int p = half*32; p < half*32 + 32; p++) {
        float x9[9];
        #pragma unroll
        for (int m = 0; m < 9; m++) {
            int i = m / 3, j = m % 3;
            x9[m] = row_s[(i*66 + (p + j))*C_ + c];
        }
        float acc[6];
        #pragma unroll
        for (int d = 0; d < 6; d++) {
            float a = 0.f;
            #pragma unroll
            for (int m = 0; m < 9; m++)
                a = fmaf(x9[m], ws[(d*9 + m)*C_ + c], a);
            acc[d] = a;
        }
        #pragma unroll
        for (int d = 0; d < 6; d++) {
            #pragma unroll
            for (int off = 16; off > 0; off >>= 1)
                acc[d] += __shfl_xor_sync(0xffffffffu, acc[d], off);
        }
        if (lane == 0) {
            #pragma unroll
            for (int d = 0; d < 6; d++)
                partial[(p*6 + d)*4 + q] = acc[d];
        }
    }
    __syncthreads();
    for (int idx = tid; idx < 384; idx += 256) {
        int p = idx / 6, d = idx % 6;
        int D = (d < 3) ? d*6 : (d-3)*2 + 1;
        float v = b_off[D];
        #pragma unroll
        for (int qq = 0; qq < 4; qq++) v += partial[(p*6 + d)*4 + qq];
        off_s[p*6 + d] = v;
    }
    __syncthreads();
    if (tid < 64) {
        int p = tid;
        float oxs[3], oys[3];
        oxs[0] = off_s[p*6 + 0];
        oxs[1] = oxs[0] + off_s[p*6 + 1];
        oxs[2] = oxs[1] + off_s[p*6 + 2];
        oys[0] = off_s[p*6 + 3];
        oys[1] = oys[0] + off_s[p*6 + 4];
        oys[2] = oys[1] + off_s[p*6 + 5];
        float xg = p * (2.0f/63.0f) - 1.0f;
        float yg = h * (2.0f/63.0f) - 1.0f;
        float2* dst = g_smp + (size_t)((b*H_ + h)*W_ + p)*9;
        #pragma unroll
        for (int i = 0; i < 3; i++) {
            #pragma unroll
            for (int j = 0; j < 3; j++) {
                float gx = (xg + oxs[i] + 1.0f)*(W_*0.5f) - 0.5f;
                float gy = (yg + oys[j] + 1.0f)*(H_*0.5f) - 0.5f;
                dst[i*3 + j] = make_float2(gx, gy);
            }
        }
    }
}

// ---------------- Kernel C: sample + mma.sync bf16 GEMM (64-px tiles) ----------------
// 2 CTAs/SM: one CTA's gather phase overlaps the other's MMA phase.
// 8 warps = 2 m-warps (32px) x 4 n-warps (32o); warp tile 32x32, 32 acc regs.
__global__ __launch_bounds__(256,2) void k_main(
    const float* __restrict__ b_main, float* __restrict__ out)
{
    extern __shared__ char smc[];
    uint32_t sb = smem_u32(smc);
    int tid = threadIdx.x;
    int wid = tid >> 5, lane = tid & 31;

    int bid = blockIdx.x;
    int b   = bid >> 6;
    int hw0 = (bid & 63) << 6;
    const float* xb = g_x_nhwc + (size_t)b*HW_*C_;

    if (tid < 128) *(float*)(smc + SM_BIAS + tid*4) = b_main[tid];

    int m0 = (wid & 1) << 5;     // 2 m-warps of 32 px
    int o0 = (wid >> 1) << 5;    // 4 n-warps of 32 outputs

    // per-lane ldmatrix constants
    int l7   = lane & 7;
    int arow = l7 + ((lane >> 3) & 1) * 8;   // A x4 row offset
    int au   = lane >> 4;                     // A x4 unit offset
    int brow = l7 + (lane >> 4) * 8;          // B x4 row offset
    int bu   = (lane >> 3) & 1;               // B x4 unit offset

    float acc[32];
    #pragma unroll
    for (int i = 0; i < 32; i++) acc[i] = 0.f;

    for (int kk = 0; kk < 9; kk++) {
        __syncthreads();   // prev tap's ldmatrix reads done; A/W writable

        // cp.async this tap's weights (swizzled layout copied verbatim)
        {
            const char* wgh = (const char*)(g_wsw + (size_t)kk*32768);
            const char* wgl = (const char*)(g_wsw + (size_t)(9 + kk)*32768);
            uint32_t dh = sb + SM_W_HI + tid*16;
            uint32_t dl = sb + SM_W_LO + tid*16;
            #pragma unroll
            for (int i = 0; i < 8; i++)
                CP_ASYNC16(dh + i*4096, wgh + i*4096 + tid*16);
            #pragma unroll
            for (int i = 0; i < 8; i++)
                CP_ASYNC16(dl + i*4096, wgl + i*4096 + tid*16);
            CP_COMMIT();
        }

        // sample 8 px per warp into A_HI/A_LO
        for (int p = wid*8; p < wid*8 + 8; p++) {
            float2 g = g_smp[(size_t)(b*HW_ + hw0 + p)*9 + kk];
            float x0f = floorf(g.x), y0f = floorf(g.y);
            int ix = (int)x0f, iy = (int)y0f;
            float wx = g.x - x0f, wy = g.y - y0f;
            float w00 = (1.f-wx)*(1.f-wy), w01 = wx*(1.f-wy);
            float w10 = (1.f-wx)*wy,       w11 = wx*wy;
            bool vx0 = (unsigned)ix < (unsigned)W_, vx1 = (unsigned)(ix+1) < (unsigned)W_;
            bool vy0 = (unsigned)iy < (unsigned)H_, vy1 = (unsigned)(iy+1) < (unsigned)H_;
            w00 = (vx0 && vy0) ? w00 : 0.f;
            w01 = (vx1 && vy0) ? w01 : 0.f;
            w10 = (vx0 && vy1) ? w10 : 0.f;
            w11 = (vx1 && vy1) ? w11 : 0.f;
            int cx0 = min(max(ix,   0), W_-1), cx1 = min(max(ix+1, 0), W_-1);
            int cy0 = min(max(iy,   0), H_-1), cy1 = min(max(iy+1, 0), H_-1);
            const float2* r00 = (const float2*)(xb + (size_t)(cy0*W_ + cx0)*C_);
            const float2* r01 = (const float2*)(xb + (size_t)(cy0*W_ + cx1)*C_);
            const float2* r10 = (const float2*)(xb + (size_t)(cy1*W_ + cx0)*C_);
            const float2* r11 = (const float2*)(xb + (size_t)(cy1*W_ + cx1)*C_);
            #pragma unroll
            for (int q = 0; q < 2; q++) {
                int ci = q*32 + lane;   // channels {2ci, 2ci+1}
                float2 a00 = r00[ci], a01 = r01[ci], a10 = r10[ci], a11 = r11[ci];
                float v0 = a00.x*w00 + a01.x*w01 + a10.x*w10 + a11.x*w11;
                float v1 = a00.y*w00 + a01.y*w01 + a10.y*w10 + a11.y*w11;
                __nv_bfloat16 h0 = __float2bfloat16(v0);
                __nv_bfloat16 h1 = __float2bfloat16(v1);
                __nv_bfloat16 l0 = __float2bfloat16(v0 - __bfloat162float(h0));
                __nv_bfloat16 l1 = __float2bfloat16(v1 - __bfloat162float(h1));
                uint32_t hp = ((uint32_t)__bfloat16_as_ushort(h1) << 16) | __bfloat16_as_ushort(h0);
                uint32_t lp = ((uint32_t)__bfloat16_as_ushort(l1) << 16) | __bfloat16_as_ushort(l0);
                uint32_t boff = (uint32_t)(p*256 + (((ci >> 2) ^ (p & 7)) << 4) + (ci & 3)*4);
                *(uint32_t*)(smc + SM_A_HI + boff) = hp;
                *(uint32_t*)(smc + SM_A_LO + boff) = lp;
            }
        }
        CP_WAIT0();
        __syncthreads();   // A + W tiles ready

        // ---- MMA over 8 k16 steps ----
        #pragma unroll 2
        for (int step = 0; step < 8; step++) {
            int u0 = step << 1;
            uint32_t ah[2][4], al[2][4];
            #pragma unroll
            for (int mt = 0; mt < 2; mt++) {
                uint32_t aoff = (uint32_t)((m0 + mt*16 + arow)*256 + (((u0 + au) ^ l7) << 4));
                ldsm4(ah[mt][0], ah[mt][1], ah[mt][2], ah[mt][3], sb + SM_A_HI + aoff);
                ldsm4(al[mt][0], al[mt][1], al[mt][2], al[mt][3], sb + SM_A_LO + aoff);
            }
            #pragma unroll
            for (int np = 0; np < 2; np++) {
                uint32_t boff = (uint32_t)((o0 + np*16 + brow)*256 + (((u0 + bu) ^ l7) << 4));
                uint32_t bh0, bh1, bh2, bh3, bl0, bl1, bl2, bl3;
                ldsm4(bh0, bh1, bh2, bh3, sb + SM_W_HI + boff);
                ldsm4(bl0, bl1, bl2, bl3, sb + SM_W_LO + boff);
                #pragma unroll
                for (int mt = 0; mt < 2; mt++) {
                    float* d0 = &acc[(mt*4 + np*2    )*4];
                    float* d1 = &acc[(mt*4 + np*2 + 1)*4];
                    mma16816(d0, ah[mt], bh0, bh1);
                    mma16816(d0, al[mt], bh0, bh1);
                    mma16816(d0, ah[mt], bl0, bl1);
                    mma16816(d1, ah[mt], bh2, bh3);
                    mma16816(d1, al[mt], bh2, bh3);
                    mma16816(d1, ah[mt], bl2, bl3);
                }
            }
        }
    }

    // ---- epilogue: stage to smem (stride 66), coalesced STG ----
    __syncthreads();
    float* outs = (float*)(smc + SM_OUT);
    #pragma unroll
    for (int mt = 0; mt < 2; mt++) {
        #pragma unroll
        for (int nt = 0; nt < 4; nt++) {
            float* d = &acc[(mt*4 + nt)*4];
            int r = m0 + mt*16 + (lane >> 2);
            int o = o0 + nt*8 + (lane & 3)*2;
            outs[ o     *66 + r    ] = d[0];
            outs[(o + 1)*66 + r    ] = d[1];
            outs[ o     *66 + r + 8] = d[2];
            outs[(o + 1)*66 + r + 8] = d[3];
        }
    }
    __syncthreads();
    const float* bias = (const float*)(smc + SM_BIAS);
    for (int idx = tid; idx < 128*64; idx += 256) {
        int o = idx >> 6, px = idx & 63;
        out[(size_t)(b*O_ + o)*HW_ + hw0 + px] = outs[o*66 + px] + bias[o];
    }
}

// ---------------- launch ----------------
extern "C" void kernel_launch(void* const* d_in, const int* in_sizes, int n_in,
                              void* d_out, int out_size) {
    const float* x      = (const float*)d_in[0];
    const float* w_off  = (const float*)d_in[1];
    const float* b_off  = (const float*)d_in[2];
    const float* w_main = (const float*)d_in[3];
    const float* b_main = (const float*)d_in[4];
    float* out = (float*)d_out;

    const int smemB = (3*66*128 + 6*9*128 + 64*6*4 + 64*6) * 4;   // 136704 B
    cudaFuncSetAttribute(k_offset, cudaFuncAttributeMaxDynamicSharedMemorySize, smemB);
    cudaFuncSetAttribute(k_main,   cudaFuncAttributeMaxDynamicSharedMemorySize, SMEM_MAIN);

    k_transpose<<<dim3(HW_/32, C_/32, B_), dim3(32, 8)>>>(x);
    k_wprep<<<(2*9*128*128 + 255)/256, 256>>>(w_main);
    k_offset<<<B_*H_, 256, smemB>>>(w_off, b_off);
    k_main<<<B_*HW_/64, 256, SMEM_MAIN>>>(b_main, out);
}

// round 6
// speedup vs baseline: 2.4980x; 1.0478x over previous
#include <cuda_runtime.h>
#include <cuda_bf16.h>
#include <cstdint>

#define B_ 8
#define C_ 128
#define O_ 128
#define H_ 64
#define W_ 64
#define HW_ (H_*W_)

// ---------------- scratch ----------------
__device__ float  g_x_nhwc[B_*HW_*C_];          // NHWC x
__device__ float2 g_smp[B_*HW_*9];              // sample coords per (b,h,w,tap)
__device__ unsigned char g_wsw[2*9*32768];      // swizzled bf16 weights [term][tap][128o x 128c]

// ---------------- helpers ----------------
__device__ __forceinline__ uint32_t smem_u32(const void* p) {
    uint32_t a;
    asm("{ .reg .u64 t; cvta.to.shared.u64 t, %1; cvt.u32.u64 %0, t; }" : "=r"(a) : "l"(p));
    return a;
}
__device__ __forceinline__ void ldsm4(uint32_t& r0, uint32_t& r1, uint32_t& r2, uint32_t& r3,
                                      uint32_t addr) {
    asm volatile("ldmatrix.sync.aligned.m8n8.x4.shared.b16 {%0,%1,%2,%3}, [%4];"
        : "=r"(r0), "=r"(r1), "=r"(r2), "=r"(r3) : "r"(addr));
}
__device__ __forceinline__ void mma16816(float* d, const uint32_t* a, uint32_t b0, uint32_t b1) {
    asm volatile("mma.sync.aligned.m16n8k16.row.col.f32.bf16.bf16.f32 "
        "{%0,%1,%2,%3}, {%4,%5,%6,%7}, {%8,%9}, {%0,%1,%2,%3};"
        : "+f"(d[0]), "+f"(d[1]), "+f"(d[2]), "+f"(d[3])
        : "r"(a[0]), "r"(a[1]), "r"(a[2]), "r"(a[3]), "r"(b0), "r"(b1));
}
#define CP_ASYNC16(dst, src) \
    asm volatile("cp.async.cg.shared.global [%0], [%1], 16;" :: "r"(dst), "l"(src))
#define CP_COMMIT() asm volatile("cp.async.commit_group;" ::: "memory")
#define CP_WAIT0()  asm volatile("cp.async.wait_group 0;" ::: "memory")

// smem map for k_main (64-px tile): 97.25 KB -> 2 CTAs/SM
#define SM_BIAS 0
#define SM_A_HI 1024
#define SM_A_LO (1024 + 16384)
#define SM_W_HI (1024 + 32768)
#define SM_W_LO (1024 + 65536)
#define SM_OUT  SM_W_HI                 // reused after last MMA
#define SMEM_MAIN (1024 + 98304)        // 99328 B

// prep fused-kernel block ranges
#define NB_TRANS 4096   // transpose: 128 x 4 x 8
#define NB_WPREP 1152   // 2*9*128*128 / 256
#define NB_OFF   512    // B_*H_
#define SMEM_PREP 35328 // offset path: ws 27648 + partial 6144 + off_s 1536

// ---------------- Fused prep kernel ----------------
// [0, 4096):       NCHW -> NHWC transpose
// [4096, 5248):    weight split + swizzle
// [5248, 5760):    offset conv (reads NCHW x directly) + grid coords
__global__ __launch_bounds__(256) void k_prep(
    const float* __restrict__ x, const float* __restrict__ w_off,
    const float* __restrict__ b_off, const float* __restrict__ w_main)
{
    extern __shared__ float smf[];
    int tid = threadIdx.x;
    int bid = blockIdx.x;

    if (bid < NB_TRANS) {
        // ---- transpose ----
        float (*tile)[33] = (float(*)[33])smf;
        int b   = bid >> 9;
        int c0  = ((bid >> 7) & 3) * 32;
        int hw0 = (bid & 127) * 32;
        int tx = tid & 31, ty = tid >> 5;
        #pragma unroll
        for (int m = 0; m < 32; m += 8)
            tile[ty + m][tx] = x[(size_t)(b*C_ + c0 + ty + m)*HW_ + hw0 + tx];
        __syncthreads();
        #pragma unroll
        for (int m = 0; m < 32; m += 8)
            g_x_nhwc[(size_t)(b*HW_ + hw0 + ty + m)*C_ + c0 + tx] = tile[tx][ty + m];
        return;
    }
    if (bid < NB_TRANS + NB_WPREP) {
        // ---- weight split + swizzle ----
        int idx = (bid - NB_TRANS) * 256 + tid;
        int c  = idx & 127;
        int o  = (idx >> 7) & 127;
        int kk = (idx >> 14) % 9;
        int t  = idx / (9*16384);
        float w = w_main[(o*C_ + c)*9 + kk];
        __nv_bfloat16 hi = __float2bfloat16(w);
        __nv_bfloat16 v  = (t == 0) ? hi : __float2bfloat16(w - __bfloat162float(hi));
        uint32_t boff = (uint32_t)(o*256 + (((c >> 3) ^ (o & 7)) << 4) + (c & 7)*2);
        *(__nv_bfloat16*)(g_wsw + (size_t)(t*9 + kk)*32768 + boff) = v;
        return;
    }

    // ---- offset conv from NCHW + grid coords ----
    float* ws      = smf;                 // 6*9*128
    float* partial = ws + 6*9*128;        // 64*6*4
    float* off_s   = partial + 64*6*4;    // 64*6

    int obid = bid - (NB_TRANS + NB_WPREP);
    int b = obid >> 6;
    int h = obid & 63;

    // stage the 6 needed weight channels: dd<3 -> D=6*dd (x), dd>=3 -> D=2*(dd-3)+1 (y)
    for (int idx = tid; idx < 6*9*128; idx += 256) {
        int c  = idx & 127;
        int m  = (idx >> 7) % 9;
        int dd = idx / (9*128);
        int D  = (dd < 3) ? dd*6 : (dd-3)*2 + 1;
        ws[idx] = w_off[(D*C_ + c)*9 + m];
    }
    __syncthreads();

    int p = tid & 63;        // pixel (coalesced across lanes)
    int q = tid >> 6;        // channel quarter
    float acc[6] = {0.f, 0.f, 0.f, 0.f, 0.f, 0.f};
    #pragma unroll 1
    for (int c32 = 0; c32 < 32; c32++) {
        int cc = q*32 + c32;
        const float* rowc = x + (size_t)(b*C_ + cc)*HW_;
        #pragma unroll
        for (int i = 0; i < 3; i++) {
            int y = h - 1 + i;
            if ((unsigned)y < (unsigned)H_) {
                const float* row = rowc + y*W_;
                float xm1 = (p > 0)      ? row[p-1] : 0.f;
                float x0  =               row[p];
                float xp1 = (p < W_-1)   ? row[p+1] : 0.f;
                #pragma unroll
                for (int d = 0; d < 6; d++) {
                    const float* wsd = ws + (d*9 + i*3)*128 + cc;
                    acc[d] = fmaf(xm1, wsd[0],     acc[d]);
                    acc[d] = fmaf(x0,  wsd[128],   acc[d]);
                    acc[d] = fmaf(xp1, wsd[256],   acc[d]);
                }
            }
        }
    }
    #pragma unroll
    for (int d = 0; d < 6; d++)
        partial[(p*6 + d)*4 + q] = acc[d];
    __syncthreads();

    for (int idx = tid; idx < 384; idx += 256) {
        int pp = idx / 6, d = idx % 6;
        int D = (d < 3) ? d*6 : (d-3)*2 + 1;
        float v = b_off[D];
        #pragma unroll
        for (int qq = 0; qq < 4; qq++) v += partial[(pp*6 + d)*4 + qq];
        off_s[pp*6 + d] = v;
    }
    __syncthreads();
    if (tid < 64) {
        int pp = tid;
        float oxs[3], oys[3];
        oxs[0] = off_s[pp*6 + 0];
        oxs[1] = oxs[0] + off_s[pp*6 + 1];
        oxs[2] = oxs[1] + off_s[pp*6 + 2];
        oys[0] = off_s[pp*6 + 3];
        oys[1] = oys[0] + off_s[pp*6 + 4];
        oys[2] = oys[1] + off_s[pp*6 + 5];
        float xg = pp * (2.0f/63.0f) - 1.0f;
        float yg = h  * (2.0f/63.0f) - 1.0f;
        float2* dst = g_smp + (size_t)((b*H_ + h)*W_ + pp)*9;
        #pragma unroll
        for (int i = 0; i < 3; i++) {
            #pragma unroll
            for (int j = 0; j < 3; j++) {
                float gx = (xg + oxs[i] + 1.0f)*(W_*0.5f) - 0.5f;
                float gy = (yg + oys[j] + 1.0f)*(H_*0.5f) - 0.5f;
                dst[i*3 + j] = make_float2(gx, gy);
            }
        }
    }
}

// ---------------- Kernel C: sample + mma.sync bf16 GEMM (64-px tiles) ----------------
// 2 CTAs/SM: one CTA's gather phase overlaps the other's MMA phase.
// 8 warps = 2 m-warps (32px) x 4 n-warps (32o); warp tile 32x32, 32 acc regs.
__global__ __launch_bounds__(256,2) void k_main(
    const float* __restrict__ b_main, float* __restrict__ out)
{
    extern __shared__ char smc[];
    uint32_t sb = smem_u32(smc);
    int tid = threadIdx.x;
    int wid = tid >> 5, lane = tid & 31;

    int bid = blockIdx.x;
    int b   = bid >> 6;
    int hw0 = (bid & 63) << 6;
    const float* xb = g_x_nhwc + (size_t)b*HW_*C_;

    if (tid < 128) *(float*)(smc + SM_BIAS + tid*4) = b_main[tid];

    int m0 = (wid & 1) << 5;     // 2 m-warps of 32 px
    int o0 = (wid >> 1) << 5;    // 4 n-warps of 32 outputs

    int l7   = lane & 7;
    int arow = l7 + ((lane >> 3) & 1) * 8;
    int au   = lane >> 4;
    int brow = l7 + (lane >> 4) * 8;
    int bu   = (lane >> 3) & 1;

    float acc[32];
    #pragma unroll
    for (int i = 0; i < 32; i++) acc[i] = 0.f;

    for (int kk = 0; kk < 9; kk++) {
        __syncthreads();

        {
            const char* wgh = (const char*)(g_wsw + (size_t)kk*32768);
            const char* wgl = (const char*)(g_wsw + (size_t)(9 + kk)*32768);
            uint32_t dh = sb + SM_W_HI + tid*16;
            uint32_t dl = sb + SM_W_LO + tid*16;
            #pragma unroll
            for (int i = 0; i < 8; i++)
                CP_ASYNC16(dh + i*4096, wgh + i*4096 + tid*16);
            #pragma unroll
            for (int i = 0; i < 8; i++)
                CP_ASYNC16(dl + i*4096, wgl + i*4096 + tid*16);
            CP_COMMIT();
        }

        for (int p = wid*8; p < wid*8 + 8; p++) {
            float2 g = g_smp[(size_t)(b*HW_ + hw0 + p)*9 + kk];
            float x0f = floorf(g.x), y0f = floorf(g.y);
            int ix = (int)x0f, iy = (int)y0f;
            float wx = g.x - x0f, wy = g.y - y0f;
            float w00 = (1.f-wx)*(1.f-wy), w01 = wx*(1.f-wy);
            float w10 = (1.f-wx)*wy,       w11 = wx*wy;
            bool vx0 = (unsigned)ix < (unsigned)W_, vx1 = (unsigned)(ix+1) < (unsigned)W_;
            bool vy0 = (unsigned)iy < (unsigned)H_, vy1 = (unsigned)(iy+1) < (unsigned)H_;
            w00 = (vx0 && vy0) ? w00 : 0.f;
            w01 = (vx1 && vy0) ? w01 : 0.f;
            w10 = (vx0 && vy1) ? w10 : 0.f;
            w11 = (vx1 && vy1) ? w11 : 0.f;
            int cx0 = min(max(ix,   0), W_-1), cx1 = min(max(ix+1, 0), W_-1);
            int cy0 = min(max(iy,   0), H_-1), cy1 = min(max(iy+1, 0), H_-1);
            const float2* r00 = (const float2*)(xb + (size_t)(cy0*W_ + cx0)*C_);
            const float2* r01 = (const float2*)(xb + (size_t)(cy0*W_ + cx1)*C_);
            const float2* r10 = (const float2*)(xb + (size_t)(cy1*W_ + cx0)*C_);
            const float2* r11 = (const float2*)(xb + (size_t)(cy1*W_ + cx1)*C_);
            #pragma unroll
            for (int q = 0; q < 2; q++) {
                int ci = q*32 + lane;
                float2 a00 = r00[ci], a01 = r01[ci], a10 = r10[ci], a11 = r11[ci];
                float v0 = a00.x*w00 + a01.x*w01 + a10.x*w10 + a11.x*w11;
                float v1 = a00.y*w00 + a01.y*w01 + a10.y*w10 + a11.y*w11;
                __nv_bfloat16 h0 = __float2bfloat16(v0);
                __nv_bfloat16 h1 = __float2bfloat16(v1);
                __nv_bfloat16 l0 = __float2bfloat16(v0 - __bfloat162float(h0));
                __nv_bfloat16 l1 = __float2bfloat16(v1 - __bfloat162float(h1));
                uint32_t hp = ((uint32_t)__bfloat16_as_ushort(h1) << 16) | __bfloat16_as_ushort(h0);
                uint32_t lp = ((uint32_t)__bfloat16_as_ushort(l1) << 16) | __bfloat16_as_ushort(l0);
                uint32_t boff = (uint32_t)(p*256 + (((ci >> 2) ^ (p & 7)) << 4) + (ci & 3)*4);
                *(uint32_t*)(smc + SM_A_HI + boff) = hp;
                *(uint32_t*)(smc + SM_A_LO + boff) = lp;
            }
        }
        CP_WAIT0();
        __syncthreads();

        #pragma unroll 2
        for (int step = 0; step < 8; step++) {
            int u0 = step << 1;
            uint32_t ah[2][4], al[2][4];
            #pragma unroll
            for (int mt = 0; mt < 2; mt++) {
                uint32_t aoff = (uint32_t)((m0 + mt*16 + arow)*256 + (((u0 + au) ^ l7) << 4));
                ldsm4(ah[mt][0], ah[mt][1], ah[mt][2], ah[mt][3], sb + SM_A_HI + aoff);
                ldsm4(al[mt][0], al[mt][1], al[mt][2], al[mt][3], sb + SM_A_LO + aoff);
            }
            #pragma unroll
            for (int np = 0; np < 2; np++) {
                uint32_t boff = (uint32_t)((o0 + np*16 + brow)*256 + (((u0 + bu) ^ l7) << 4));
                uint32_t bh0, bh1, bh2, bh3, bl0, bl1, bl2, bl3;
                ldsm4(bh0, bh1, bh2, bh3, sb + SM_W_HI + boff);
                ldsm4(bl0, bl1, bl2, bl3, sb + SM_W_LO + boff);
                #pragma unroll
                for (int mt = 0; mt < 2; mt++) {
                    float* d0 = &acc[(mt*4 + np*2    )*4];
                    float* d1 = &acc[(mt*4 + np*2 + 1)*4];
                    mma16816(d0, ah[mt], bh0, bh1);
                    mma16816(d0, al[mt], bh0, bh1);
                    mma16816(d0, ah[mt], bl0, bl1);
                    mma16816(d1, ah[mt], bh2, bh3);
                    mma16816(d1, al[mt], bh2, bh3);
                    mma16816(d1, ah[mt], bl2, bl3);
                }
            }
        }
    }

    __syncthreads();
    float* outs = (float*)(smc + SM_OUT);
    #pragma unroll
    for (int mt = 0; mt < 2; mt++) {
        #pragma unroll
        for (int nt = 0; nt < 4; nt++) {
            float* d = &acc[(mt*4 + nt)*4];
            int r = m0 + mt*16 + (lane >> 2);
            int o = o0 + nt*8 + (lane & 3)*2;
            outs[ o     *66 + r    ] = d[0];
            outs[(o + 1)*66 + r    ] = d[1];
            outs[ o     *66 + r + 8] = d[2];
            outs[(o + 1)*66 + r + 8] = d[3];
        }
    }
    __syncthreads();
    const float* bias = (const float*)(smc + SM_BIAS);
    for (int idx = tid; idx < 128*64; idx += 256) {
        int o = idx >> 6, px = idx & 63;
        out[(size_t)(b*O_ + o)*HW_ + hw0 + px] = outs[o*66 + px] + bias[o];
    }
}

// ---------------- launch ----------------
extern "C" void kernel_launch(void* const* d_in, const int* in_sizes, int n_in,
                              void* d_out, int out_size) {
    const float* x      = (const float*)d_in[0];
    const float* w_off  = (const float*)d_in[1];
    const float* b_off  = (const float*)d_in[2];
    const float* w_main = (const float*)d_in[3];
    const float* b_main = (const float*)d_in[4];
    float* out = (float*)d_out;

    cudaFuncSetAttribute(k_prep, cudaFuncAttributeMaxDynamicSharedMemorySize, SMEM_PREP);
    cudaFuncSetAttribute(k_main, cudaFuncAttributeMaxDynamicSharedMemorySize, SMEM_MAIN);

    k_prep<<<NB_TRANS + NB_WPREP + NB_OFF, 256, SMEM_PREP>>>(x, w_off, b_off, w_main);
    k_main<<<B_*HW_/64, 256, SMEM_MAIN>>>(b_main, out);
}